// round 2
// baseline (speedup 1.0000x reference)
#include <cuda_runtime.h>
#include <cuda_bf16.h>
#include <cstdint>
#include <cstddef>

// ---------------------------------------------------------------------------
// Fixed problem shape:
// x: (2, 256, 256, 256) fp32, windows 8x8 -> 32x32 window grid per image.
// token = ((b*32 + wx)*32 + wy)*64 + w1*8 + w2 ;  H = wx*8+w1, W = wy*8+w2
// ---------------------------------------------------------------------------
#define NTOK  131072

constexpr size_t NT = (size_t)NTOK;
constexpr size_t OFF_XW    = 0;              // [NTOK,256] gathered x (residual 1)
constexpr size_t OFF_T     = NT * 256;       // [NTOK,256] ln2(ln1(xw)); reused for final y
constexpr size_t OFF_QKV   = NT * 512;       // [NTOK,768]
constexpr size_t OFF_ATTNO = NT * 1280;      // [NTOK,256] attention output (pre-proj)
constexpr size_t OFF_XW2   = NT * 1536;      // [NTOK,256] xw + proj (residual 2)
constexpr size_t OFF_F     = NT * 1792;      // [NTOK,256] ln3(xw2)
constexpr size_t OFF_H     = NT * 2048;      // [NTOK,1024] gelu hidden

__device__ float g_scratch[NT * 3072];       // ~1.61 GB

// ---------------------------------------------------------------------------
// K1: gather NCHW -> token-major xw. Block = (b, wx, w1, dchunk of 32).
// Reads one full image row per d (coalesced); writes 128B token segments.
// ---------------------------------------------------------------------------
__global__ void __launch_bounds__(256) k_gather(const float* __restrict__ x)
{
    __shared__ float sm[256][33];
    const int tid = threadIdx.x;
    const int bi  = blockIdx.x;
    const int dc  = bi & 7;
    const int w1  = (bi >> 3) & 7;
    const int wx  = (bi >> 6) & 31;
    const int b   = bi >> 11;
    const int hh  = wx * 8 + w1;

    const float* xb = x + ((size_t)b * 256 + dc * 32) * 65536 + (size_t)hh * 256;
#pragma unroll
    for (int it = 0; it < 32; ++it)
        sm[tid][it] = xb[(size_t)it * 65536 + tid];
    __syncthreads();

#pragma unroll
    for (int it = 0; it < 32; ++it) {
        int t  = it * 8 + (tid >> 5);   // W coordinate 0..255
        int dd = tid & 31;
        size_t tok = (((size_t)b * 32 + wx) * 32 + (t >> 3)) * 64 + w1 * 8 + (t & 7);
        g_scratch[OFF_XW + tok * 256 + dc * 32 + dd] = sm[t][dd];
    }
}

// ---------------------------------------------------------------------------
// K9: scatter token-major y (OFF_T) -> NCHW output. Inverse of k_gather.
// ---------------------------------------------------------------------------
__global__ void __launch_bounds__(256) k_scatter(float* __restrict__ out)
{
    __shared__ float sm[256][33];
    const int tid = threadIdx.x;
    const int bi  = blockIdx.x;
    const int dc  = bi & 7;
    const int w1  = (bi >> 3) & 7;
    const int wx  = (bi >> 6) & 31;
    const int b   = bi >> 11;
    const int hh  = wx * 8 + w1;

#pragma unroll
    for (int it = 0; it < 32; ++it) {
        int t  = it * 8 + (tid >> 5);
        int dd = tid & 31;
        size_t tok = (((size_t)b * 32 + wx) * 32 + (t >> 3)) * 64 + w1 * 8 + (t & 7);
        sm[t][dd] = g_scratch[OFF_T + tok * 256 + dc * 32 + dd];
    }
    __syncthreads();

    float* ob = out + ((size_t)b * 256 + dc * 32) * 65536 + (size_t)hh * 256;
#pragma unroll
    for (int it = 0; it < 32; ++it)
        ob[(size_t)it * 65536 + tid] = sm[tid][it];
}

// ---------------------------------------------------------------------------
// K2: fused LN1 then LN2: reads OFF_XW, writes OFF_T. Block = 32 tokens.
// ---------------------------------------------------------------------------
__global__ void __launch_bounds__(256) k_ln12(
    const float* __restrict__ g1, const float* __restrict__ b1,
    const float* __restrict__ g2, const float* __restrict__ b2)
{
    __shared__ float sm[32 * 256];
    __shared__ float sg1[256], sb1[256], sg2[256], sb2[256];
    __shared__ float st1[32][2], st2[32][2];

    const int tid = threadIdx.x;
    const size_t base = (size_t)blockIdx.x * 32 * 256;
    sg1[tid] = g1[tid]; sb1[tid] = b1[tid];
    sg2[tid] = g2[tid]; sb2[tid] = b2[tid];

    const float* src = g_scratch + OFF_XW + base;
#pragma unroll
    for (int it = 0; it < 32; ++it)
        sm[it * 256 + tid] = src[it * 256 + tid];
    __syncthreads();

    const int warp = tid >> 5, lane = tid & 31;
#pragma unroll
    for (int j = 0; j < 4; ++j) {
        int tok = warp * 4 + j;
        float s = 0.f, ss = 0.f;
#pragma unroll
        for (int m = 0; m < 8; ++m) {
            float v = sm[tok * 256 + lane + 32 * m];
            s += v; ss += v * v;
        }
#pragma unroll
        for (int o = 16; o > 0; o >>= 1) {
            s  += __shfl_xor_sync(0xffffffffu, s, o);
            ss += __shfl_xor_sync(0xffffffffu, ss, o);
        }
        float m1 = s * (1.f / 256.f);
        float v1 = ss * (1.f / 256.f) - m1 * m1;
        float i1 = rsqrtf(v1 + 1e-5f);
        if (lane == 0) { st1[tok][0] = m1; st1[tok][1] = i1; }

        float s2 = 0.f, ss2 = 0.f;
#pragma unroll
        for (int m = 0; m < 8; ++m) {
            int d = lane + 32 * m;
            float u = (sm[tok * 256 + d] - m1) * i1 * sg1[d] + sb1[d];
            s2 += u; ss2 += u * u;
        }
#pragma unroll
        for (int o = 16; o > 0; o >>= 1) {
            s2  += __shfl_xor_sync(0xffffffffu, s2, o);
            ss2 += __shfl_xor_sync(0xffffffffu, ss2, o);
        }
        if (lane == 0) {
            float m2 = s2 * (1.f / 256.f);
            float v2 = ss2 * (1.f / 256.f) - m2 * m2;
            st2[tok][0] = m2; st2[tok][1] = rsqrtf(v2 + 1e-5f);
        }
    }
    __syncthreads();

    float* dst = g_scratch + OFF_T + base;
#pragma unroll
    for (int tok = 0; tok < 32; ++tok) {
        float v = sm[tok * 256 + tid];
        float u = (v - st1[tok][0]) * st1[tok][1] * sg1[tid] + sb1[tid];
        dst[tok * 256 + tid] = (u - st2[tok][0]) * st2[tok][1] * sg2[tid] + sb2[tid];
    }
}

// ---------------------------------------------------------------------------
// K6: LN3: reads OFF_XW2, writes OFF_F. Block = 32 tokens.
// ---------------------------------------------------------------------------
__global__ void __launch_bounds__(256) k_ln3(
    const float* __restrict__ g3, const float* __restrict__ b3)
{
    __shared__ float sm[32 * 256];
    __shared__ float sg[256], sb[256];
    __shared__ float st[32][2];

    const int tid = threadIdx.x;
    const size_t base = (size_t)blockIdx.x * 32 * 256;
    sg[tid] = g3[tid]; sb[tid] = b3[tid];

    const float* src = g_scratch + OFF_XW2 + base;
#pragma unroll
    for (int it = 0; it < 32; ++it)
        sm[it * 256 + tid] = src[it * 256 + tid];
    __syncthreads();

    const int warp = tid >> 5, lane = tid & 31;
#pragma unroll
    for (int j = 0; j < 4; ++j) {
        int tok = warp * 4 + j;
        float s = 0.f, ss = 0.f;
#pragma unroll
        for (int m = 0; m < 8; ++m) {
            float v = sm[tok * 256 + lane + 32 * m];
            s += v; ss += v * v;
        }
#pragma unroll
        for (int o = 16; o > 0; o >>= 1) {
            s  += __shfl_xor_sync(0xffffffffu, s, o);
            ss += __shfl_xor_sync(0xffffffffu, ss, o);
        }
        if (lane == 0) {
            float m = s * (1.f / 256.f);
            float v = ss * (1.f / 256.f) - m * m;
            st[tok][0] = m; st[tok][1] = rsqrtf(v + 1e-5f);
        }
    }
    __syncthreads();

    float* dst = g_scratch + OFF_F + base;
#pragma unroll
    for (int tok = 0; tok < 32; ++tok) {
        float v = sm[tok * 256 + tid];
        dst[tok * 256 + tid] = (v - st[tok][0]) * st[tok][1] * sg[tid] + sb[tid];
    }
}

// ---------------------------------------------------------------------------
// GEMM: C[M,N] = A[M,K] @ B[K,N] (+ epilogue), row-major, all dims %128/%16==0.
// 128x128 tile, BK=16, 256 threads, 8x8 per thread, double-buffered SMEM.
// EPI: 0 none | 1 +RES | 2 gelu(acc+BIAS) | 3 acc+BIAS+RES
// ---------------------------------------------------------------------------
__device__ __forceinline__ void gemm_compute(
    const float (*As)[132], const float (*Bs)[128],
    int tm, int tn, float acc[8][8])
{
#pragma unroll
    for (int kk = 0; kk < 16; ++kk) {
        float4 xa0 = *(const float4*)&As[kk][tm];
        float4 xa1 = *(const float4*)&As[kk][tm + 4];
        float4 xb0 = *(const float4*)&Bs[kk][tn];
        float4 xb1 = *(const float4*)&Bs[kk][tn + 4];
        float av[8] = {xa0.x, xa0.y, xa0.z, xa0.w, xa1.x, xa1.y, xa1.z, xa1.w};
        float bv[8] = {xb0.x, xb0.y, xb0.z, xb0.w, xb1.x, xb1.y, xb1.z, xb1.w};
#pragma unroll
        for (int i = 0; i < 8; ++i)
#pragma unroll
            for (int j = 0; j < 8; ++j)
                acc[i][j] += av[i] * bv[j];
    }
}

template <int EPI>
__global__ void __launch_bounds__(256, 2) k_gemm(
    const float* __restrict__ A, const float* __restrict__ B,
    float* __restrict__ C, const float* __restrict__ RES,
    const float* __restrict__ BIAS, int N, int K)
{
    __shared__ float As[2][16][132];
    __shared__ float Bs[2][16][128];

    const int tid = threadIdx.x;
    const int bm = blockIdx.y << 7, bn = blockIdx.x << 7;
    const int arow = tid >> 2, acol = (tid & 3) << 2;
    const int brow = tid >> 5, bcol = (tid & 31) << 2;

    const float* Ap = A + (size_t)(bm + arow) * K + acol;
    const float* Bp = B + (size_t)brow * N + bn + bcol;
    const size_t A64 = (size_t)64 * K;
    const size_t B8  = (size_t)8 * N;

    float4 a0 = *(const float4*)Ap;
    float4 a1 = *(const float4*)(Ap + A64);
    float4 b0 = *(const float4*)Bp;
    float4 b1 = *(const float4*)(Bp + B8);

    As[0][acol + 0][arow] = a0.x; As[0][acol + 1][arow] = a0.y;
    As[0][acol + 2][arow] = a0.z; As[0][acol + 3][arow] = a0.w;
    As[0][acol + 0][arow + 64] = a1.x; As[0][acol + 1][arow + 64] = a1.y;
    As[0][acol + 2][arow + 64] = a1.z; As[0][acol + 3][arow + 64] = a1.w;
    *(float4*)&Bs[0][brow][bcol]     = b0;
    *(float4*)&Bs[0][brow + 8][bcol] = b1;
    __syncthreads();

    float acc[8][8];
#pragma unroll
    for (int i = 0; i < 8; ++i)
#pragma unroll
        for (int j = 0; j < 8; ++j) acc[i][j] = 0.f;

    const int tm = (tid >> 4) << 3, tn = (tid & 15) << 3;
    int buf = 0;

    for (int kt = 16; kt < K; kt += 16) {
        Ap += 16;
        Bp += (size_t)16 * N;
        a0 = *(const float4*)Ap;
        a1 = *(const float4*)(Ap + A64);
        b0 = *(const float4*)Bp;
        b1 = *(const float4*)(Bp + B8);

        gemm_compute(As[buf], Bs[buf], tm, tn, acc);

        int nb = buf ^ 1;
        As[nb][acol + 0][arow] = a0.x; As[nb][acol + 1][arow] = a0.y;
        As[nb][acol + 2][arow] = a0.z; As[nb][acol + 3][arow] = a0.w;
        As[nb][acol + 0][arow + 64] = a1.x; As[nb][acol + 1][arow + 64] = a1.y;
        As[nb][acol + 2][arow + 64] = a1.z; As[nb][acol + 3][arow + 64] = a1.w;
        *(float4*)&Bs[nb][brow][bcol]     = b0;
        *(float4*)&Bs[nb][brow + 8][bcol] = b1;
        __syncthreads();
        buf = nb;
    }
    gemm_compute(As[buf], Bs[buf], tm, tn, acc);

    // epilogue
#pragma unroll
    for (int i = 0; i < 8; ++i) {
        size_t r = (size_t)(bm + tm + i);
        float* cp = C + r * N + bn + tn;
        const float* rp = RES + r * N + bn + tn;
        float vals[8];
#pragma unroll
        for (int j = 0; j < 8; ++j) {
            float v = acc[i][j];
            if (EPI == 1) v += rp[j];
            if (EPI == 2) { v += BIAS[bn + tn + j]; v = v * normcdff(v); }
            if (EPI == 3) v += BIAS[bn + tn + j] + rp[j];
            vals[j] = v;
        }
        *(float4*)cp       = make_float4(vals[0], vals[1], vals[2], vals[3]);
        *(float4*)(cp + 4) = make_float4(vals[4], vals[5], vals[6], vals[7]);
    }
}

// ---------------------------------------------------------------------------
// K4: windowed attention. One block (256 thr) per window; loop over 8 heads.
// Reads OFF_QKV, writes OFF_ATTNO (heads merged token-major).
// ---------------------------------------------------------------------------
__global__ void __launch_bounds__(256) k_attn(const float* __restrict__ rpb)
{
    __shared__ float sq[64][32];
    __shared__ float sk[64][33];
    __shared__ float sv[64][33];
    __shared__ float sp[64][65];
    __shared__ float srpb[225 * 8];

    const int tid = threadIdx.x;
    const size_t tokbase = (size_t)blockIdx.x * 64;
    const float* qkv = g_scratch + OFF_QKV;
    float* outp = g_scratch + OFF_ATTNO;

    for (int i = tid; i < 1800; i += 256) srpb[i] = rpb[i];

    const int row = tid >> 2, c = tid & 3;
    const int ri = row >> 3, rj = row & 7;
    const float sc = 0.17677669529663687f; // 32^-0.5

    for (int h = 0; h < 8; ++h) {
        __syncthreads();  // protect smem reuse across heads (incl. srpb fill)
        // load q,k,v for this head
#pragma unroll
        for (int m = 0; m < 2; ++m) {
            int e = m * 256 + tid;
            int t = e >> 3, d4 = (e & 7) << 2;
            const float* src = qkv + (tokbase + t) * 768 + h * 32 + d4;
            float4 q4 = *(const float4*)src;
            float4 k4 = *(const float4*)(src + 256);
            float4 v4 = *(const float4*)(src + 512);
            q4.x *= sc; q4.y *= sc; q4.z *= sc; q4.w *= sc;
            *(float4*)&sq[t][d4] = q4;
            sk[t][d4 + 0] = k4.x; sk[t][d4 + 1] = k4.y;
            sk[t][d4 + 2] = k4.z; sk[t][d4 + 3] = k4.w;
            sv[t][d4 + 0] = v4.x; sv[t][d4 + 1] = v4.y;
            sv[t][d4 + 2] = v4.z; sv[t][d4 + 3] = v4.w;
        }
        __syncthreads();

        // sim row = q[row] . k[col], 16 cols per thread
        float s[16];
#pragma unroll
        for (int j = 0; j < 16; ++j) s[j] = 0.f;
#pragma unroll
        for (int d = 0; d < 32; ++d) {
            float qv = sq[row][d];
#pragma unroll
            for (int j = 0; j < 16; ++j)
                s[j] += qv * sk[c * 16 + j][d];
        }
        // + relative position bias
#pragma unroll
        for (int j = 0; j < 16; ++j) {
            int col = c * 16 + j;
            int idx = (ri - (col >> 3) + 7) * 15 + (rj - (col & 7) + 7);
            s[j] += srpb[idx * 8 + h];
        }
        // softmax across the 4-lane quad owning this row
        float mx = s[0];
#pragma unroll
        for (int j = 1; j < 16; ++j) mx = fmaxf(mx, s[j]);
        mx = fmaxf(mx, __shfl_xor_sync(0xffffffffu, mx, 1));
        mx = fmaxf(mx, __shfl_xor_sync(0xffffffffu, mx, 2));
        float sum = 0.f;
#pragma unroll
        for (int j = 0; j < 16; ++j) { s[j] = __expf(s[j] - mx); sum += s[j]; }
        sum += __shfl_xor_sync(0xffffffffu, sum, 1);
        sum += __shfl_xor_sync(0xffffffffu, sum, 2);
        float inv = 1.f / sum;
#pragma unroll
        for (int j = 0; j < 16; ++j) sp[row][c * 16 + j] = s[j] * inv;
        __syncthreads();

        // out[row][c*8 .. c*8+7] = sum_j p[row][j] * v[j][:]
        float o[8];
#pragma unroll
        for (int dd = 0; dd < 8; ++dd) o[dd] = 0.f;
#pragma unroll
        for (int jc = 0; jc < 64; ++jc) {
            float p = sp[row][jc];
#pragma unroll
            for (int dd = 0; dd < 8; ++dd)
                o[dd] += p * sv[jc][c * 8 + dd];
        }
        float* dst = outp + (tokbase + row) * 256 + h * 32 + c * 8;
        *(float4*)dst       = make_float4(o[0], o[1], o[2], o[3]);
        *(float4*)(dst + 4) = make_float4(o[4], o[5], o[6], o[7]);
    }
}

// ---------------------------------------------------------------------------
// Host launcher
// ---------------------------------------------------------------------------
extern "C" void kernel_launch(void* const* d_in, const int* in_sizes, int n_in,
                              void* d_out, int out_size)
{
    const float* x     = (const float*)d_in[0];
    const float* ln1_g = (const float*)d_in[1];
    const float* ln1_b = (const float*)d_in[2];
    const float* ln2_g = (const float*)d_in[3];
    const float* ln2_b = (const float*)d_in[4];
    const float* w_qkv = (const float*)d_in[5];
    const float* w_out = (const float*)d_in[6];
    const float* rpb   = (const float*)d_in[7];
    const float* ln3_g = (const float*)d_in[8];
    const float* ln3_b = (const float*)d_in[9];
    const float* w1    = (const float*)d_in[10];
    const float* b1    = (const float*)d_in[11];
    const float* w2    = (const float*)d_in[12];
    const float* b2    = (const float*)d_in[13];
    float* out = (float*)d_out;

    float* S = nullptr;
    cudaGetSymbolAddress((void**)&S, g_scratch);

    // 1. gather x -> xw (token-major)
    k_gather<<<4096, 256>>>(x);
    // 2. t = LN2(LN1(xw))
    k_ln12<<<4096, 256>>>(ln1_g, ln1_b, ln2_g, ln2_b);
    // 3. qkv = t @ w_qkv          [131072 x 768] = [131072 x 256] @ [256 x 768]
    k_gemm<0><<<dim3(6, 1024), 256>>>(S + OFF_T, w_qkv, S + OFF_QKV, S, S, 768, 256);
    // 4. windowed attention -> attno
    k_attn<<<2048, 256>>>(rpb);
    // 5. xw2 = attno @ w_out + xw
    k_gemm<1><<<dim3(2, 1024), 256>>>(S + OFF_ATTNO, w_out, S + OFF_XW2, S + OFF_XW, S, 256, 256);
    // 6. f = LN3(xw2)
    k_ln3<<<4096, 256>>>(ln3_g, ln3_b);
    // 7. h = gelu(f @ w1 + b1)    [131072 x 1024]
    k_gemm<2><<<dim3(8, 1024), 256>>>(S + OFF_F, w1, S + OFF_H, S, b1, 1024, 256);
    // 8. y = h @ w2 + b2 + xw2 -> OFF_T (reuse)
    k_gemm<3><<<dim3(2, 1024), 256>>>(S + OFF_H, w2, S + OFF_T, S + OFF_XW2, b2, 256, 1024);
    // 9. scatter y -> NCHW out
    k_scatter<<<4096, 256>>>(out);
}

// round 3
// speedup vs baseline: 1.0010x; 1.0010x over previous
#include <cuda_runtime.h>
#include <cuda_bf16.h>
#include <cstdint>
#include <cstddef>

// ---------------------------------------------------------------------------
// Fixed problem shape:
// x: (2, 256, 256, 256) fp32, windows 8x8 -> 32x32 window grid per image.
// token = ((b*32 + wx)*32 + wy)*64 + w1*8 + w2 ;  H = wx*8+w1, W = wy*8+w2
// ---------------------------------------------------------------------------
#define NTOK  131072

constexpr size_t NT = (size_t)NTOK;
constexpr size_t OFF_XW    = 0;              // [NTOK,256] gathered x (residual 1)
constexpr size_t OFF_T     = NT * 256;       // [NTOK,256] ln2(ln1(xw)); reused for final y
constexpr size_t OFF_QKV   = NT * 512;       // [NTOK,768]
constexpr size_t OFF_ATTNO = NT * 1280;      // [NTOK,256] attention output (pre-proj)
constexpr size_t OFF_XW2   = NT * 1536;      // [NTOK,256] xw + proj (residual 2)
constexpr size_t OFF_F     = NT * 1792;      // [NTOK,256] ln3(xw2)
constexpr size_t OFF_H     = NT * 2048;      // [NTOK,1024] gelu hidden

__device__ float g_scratch[NT * 3072];       // ~1.61 GB

// ---------------------------------------------------------------------------
// K1: gather NCHW -> token-major xw. Block = (b, wx, w1, dchunk of 32).
// Reads one full image row per d (coalesced); writes 128B token segments.
// ---------------------------------------------------------------------------
__global__ void __launch_bounds__(256) k_gather(const float* __restrict__ x)
{
    __shared__ float sm[256][33];
    const int tid = threadIdx.x;
    const int bi  = blockIdx.x;
    const int dc  = bi & 7;
    const int w1  = (bi >> 3) & 7;
    const int wx  = (bi >> 6) & 31;
    const int b   = bi >> 11;
    const int hh  = wx * 8 + w1;

    const float* xb = x + ((size_t)b * 256 + dc * 32) * 65536 + (size_t)hh * 256;
#pragma unroll
    for (int it = 0; it < 32; ++it)
        sm[tid][it] = xb[(size_t)it * 65536 + tid];
    __syncthreads();

#pragma unroll
    for (int it = 0; it < 32; ++it) {
        int t  = it * 8 + (tid >> 5);   // W coordinate 0..255
        int dd = tid & 31;
        size_t tok = (((size_t)b * 32 + wx) * 32 + (t >> 3)) * 64 + w1 * 8 + (t & 7);
        g_scratch[OFF_XW + tok * 256 + dc * 32 + dd] = sm[t][dd];
    }
}

// ---------------------------------------------------------------------------
// K9: scatter token-major y (OFF_T) -> NCHW output. Inverse of k_gather.
// ---------------------------------------------------------------------------
__global__ void __launch_bounds__(256) k_scatter(float* __restrict__ out)
{
    __shared__ float sm[256][33];
    const int tid = threadIdx.x;
    const int bi  = blockIdx.x;
    const int dc  = bi & 7;
    const int w1  = (bi >> 3) & 7;
    const int wx  = (bi >> 6) & 31;
    const int b   = bi >> 11;
    const int hh  = wx * 8 + w1;

#pragma unroll
    for (int it = 0; it < 32; ++it) {
        int t  = it * 8 + (tid >> 5);
        int dd = tid & 31;
        size_t tok = (((size_t)b * 32 + wx) * 32 + (t >> 3)) * 64 + w1 * 8 + (t & 7);
        sm[t][dd] = g_scratch[OFF_T + tok * 256 + dc * 32 + dd];
    }
    __syncthreads();

    float* ob = out + ((size_t)b * 256 + dc * 32) * 65536 + (size_t)hh * 256;
#pragma unroll
    for (int it = 0; it < 32; ++it)
        ob[(size_t)it * 65536 + tid] = sm[tid][it];
}

// ---------------------------------------------------------------------------
// K2: fused LN1 then LN2: reads OFF_XW, writes OFF_T. Block = 32 tokens.
// ---------------------------------------------------------------------------
__global__ void __launch_bounds__(256) k_ln12(
    const float* __restrict__ g1, const float* __restrict__ b1,
    const float* __restrict__ g2, const float* __restrict__ b2)
{
    __shared__ float sm[32 * 256];
    __shared__ float sg1[256], sb1[256], sg2[256], sb2[256];
    __shared__ float st1[32][2], st2[32][2];

    const int tid = threadIdx.x;
    const size_t base = (size_t)blockIdx.x * 32 * 256;
    sg1[tid] = g1[tid]; sb1[tid] = b1[tid];
    sg2[tid] = g2[tid]; sb2[tid] = b2[tid];

    const float* src = g_scratch + OFF_XW + base;
#pragma unroll
    for (int it = 0; it < 32; ++it)
        sm[it * 256 + tid] = src[it * 256 + tid];
    __syncthreads();

    const int warp = tid >> 5, lane = tid & 31;
#pragma unroll
    for (int j = 0; j < 4; ++j) {
        int tok = warp * 4 + j;
        float s = 0.f, ss = 0.f;
#pragma unroll
        for (int m = 0; m < 8; ++m) {
            float v = sm[tok * 256 + lane + 32 * m];
            s += v; ss += v * v;
        }
#pragma unroll
        for (int o = 16; o > 0; o >>= 1) {
            s  += __shfl_xor_sync(0xffffffffu, s, o);
            ss += __shfl_xor_sync(0xffffffffu, ss, o);
        }
        float m1 = s * (1.f / 256.f);
        float v1 = ss * (1.f / 256.f) - m1 * m1;
        float i1 = rsqrtf(v1 + 1e-5f);
        if (lane == 0) { st1[tok][0] = m1; st1[tok][1] = i1; }

        float s2 = 0.f, ss2 = 0.f;
#pragma unroll
        for (int m = 0; m < 8; ++m) {
            int d = lane + 32 * m;
            float u = (sm[tok * 256 + d] - m1) * i1 * sg1[d] + sb1[d];
            s2 += u; ss2 += u * u;
        }
#pragma unroll
        for (int o = 16; o > 0; o >>= 1) {
            s2  += __shfl_xor_sync(0xffffffffu, s2, o);
            ss2 += __shfl_xor_sync(0xffffffffu, ss2, o);
        }
        if (lane == 0) {
            float m2 = s2 * (1.f / 256.f);
            float v2 = ss2 * (1.f / 256.f) - m2 * m2;
            st2[tok][0] = m2; st2[tok][1] = rsqrtf(v2 + 1e-5f);
        }
    }
    __syncthreads();

    float* dst = g_scratch + OFF_T + base;
#pragma unroll
    for (int tok = 0; tok < 32; ++tok) {
        float v = sm[tok * 256 + tid];
        float u = (v - st1[tok][0]) * st1[tok][1] * sg1[tid] + sb1[tid];
        dst[tok * 256 + tid] = (u - st2[tok][0]) * st2[tok][1] * sg2[tid] + sb2[tid];
    }
}

// ---------------------------------------------------------------------------
// K6: LN3: reads OFF_XW2, writes OFF_F. Block = 32 tokens.
// ---------------------------------------------------------------------------
__global__ void __launch_bounds__(256) k_ln3(
    const float* __restrict__ g3, const float* __restrict__ b3)
{
    __shared__ float sm[32 * 256];
    __shared__ float sg[256], sb[256];
    __shared__ float st[32][2];

    const int tid = threadIdx.x;
    const size_t base = (size_t)blockIdx.x * 32 * 256;
    sg[tid] = g3[tid]; sb[tid] = b3[tid];

    const float* src = g_scratch + OFF_XW2 + base;
#pragma unroll
    for (int it = 0; it < 32; ++it)
        sm[it * 256 + tid] = src[it * 256 + tid];
    __syncthreads();

    const int warp = tid >> 5, lane = tid & 31;
#pragma unroll
    for (int j = 0; j < 4; ++j) {
        int tok = warp * 4 + j;
        float s = 0.f, ss = 0.f;
#pragma unroll
        for (int m = 0; m < 8; ++m) {
            float v = sm[tok * 256 + lane + 32 * m];
            s += v; ss += v * v;
        }
#pragma unroll
        for (int o = 16; o > 0; o >>= 1) {
            s  += __shfl_xor_sync(0xffffffffu, s, o);
            ss += __shfl_xor_sync(0xffffffffu, ss, o);
        }
        if (lane == 0) {
            float m = s * (1.f / 256.f);
            float v = ss * (1.f / 256.f) - m * m;
            st[tok][0] = m; st[tok][1] = rsqrtf(v + 1e-5f);
        }
    }
    __syncthreads();

    float* dst = g_scratch + OFF_F + base;
#pragma unroll
    for (int tok = 0; tok < 32; ++tok) {
        float v = sm[tok * 256 + tid];
        dst[tok * 256 + tid] = (v - st[tok][0]) * st[tok][1] * sg[tid] + sb[tid];
    }
}

// ---------------------------------------------------------------------------
// GEMM: C[M,N] = A[M,K] @ B[K,N] (+ epilogue), row-major, all dims %128/%16==0.
// 128x128 tile, BK=16, 256 threads, 8x8 per thread, double-buffered SMEM.
// EPI: 0 none | 1 +RES | 2 gelu(acc+BIAS) | 3 acc+BIAS+RES
// ---------------------------------------------------------------------------
__device__ __forceinline__ void gemm_compute(
    const float (*As)[132], const float (*Bs)[128],
    int tm, int tn, float acc[8][8])
{
#pragma unroll
    for (int kk = 0; kk < 16; ++kk) {
        float4 xa0 = *(const float4*)&As[kk][tm];
        float4 xa1 = *(const float4*)&As[kk][tm + 4];
        float4 xb0 = *(const float4*)&Bs[kk][tn];
        float4 xb1 = *(const float4*)&Bs[kk][tn + 4];
        float av[8] = {xa0.x, xa0.y, xa0.z, xa0.w, xa1.x, xa1.y, xa1.z, xa1.w};
        float bv[8] = {xb0.x, xb0.y, xb0.z, xb0.w, xb1.x, xb1.y, xb1.z, xb1.w};
#pragma unroll
        for (int i = 0; i < 8; ++i)
#pragma unroll
            for (int j = 0; j < 8; ++j)
                acc[i][j] += av[i] * bv[j];
    }
}

template <int EPI>
__global__ void __launch_bounds__(256, 2) k_gemm(
    const float* __restrict__ A, const float* __restrict__ B,
    float* __restrict__ C, const float* __restrict__ RES,
    const float* __restrict__ BIAS, int N, int K)
{
    __shared__ float As[2][16][132];
    __shared__ float Bs[2][16][128];

    const int tid = threadIdx.x;
    const int bm = blockIdx.y << 7, bn = blockIdx.x << 7;
    const int arow = tid >> 2, acol = (tid & 3) << 2;
    const int brow = tid >> 5, bcol = (tid & 31) << 2;

    const float* Ap = A + (size_t)(bm + arow) * K + acol;
    const float* Bp = B + (size_t)brow * N + bn + bcol;
    const size_t A64 = (size_t)64 * K;
    const size_t B8  = (size_t)8 * N;

    float4 a0 = *(const float4*)Ap;
    float4 a1 = *(const float4*)(Ap + A64);
    float4 b0 = *(const float4*)Bp;
    float4 b1 = *(const float4*)(Bp + B8);

    As[0][acol + 0][arow] = a0.x; As[0][acol + 1][arow] = a0.y;
    As[0][acol + 2][arow] = a0.z; As[0][acol + 3][arow] = a0.w;
    As[0][acol + 0][arow + 64] = a1.x; As[0][acol + 1][arow + 64] = a1.y;
    As[0][acol + 2][arow + 64] = a1.z; As[0][acol + 3][arow + 64] = a1.w;
    *(float4*)&Bs[0][brow][bcol]     = b0;
    *(float4*)&Bs[0][brow + 8][bcol] = b1;
    __syncthreads();

    float acc[8][8];
#pragma unroll
    for (int i = 0; i < 8; ++i)
#pragma unroll
        for (int j = 0; j < 8; ++j) acc[i][j] = 0.f;

    const int tm = (tid >> 4) << 3, tn = (tid & 15) << 3;
    int buf = 0;

    for (int kt = 16; kt < K; kt += 16) {
        Ap += 16;
        Bp += (size_t)16 * N;
        a0 = *(const float4*)Ap;
        a1 = *(const float4*)(Ap + A64);
        b0 = *(const float4*)Bp;
        b1 = *(const float4*)(Bp + B8);

        gemm_compute(As[buf], Bs[buf], tm, tn, acc);

        int nb = buf ^ 1;
        As[nb][acol + 0][arow] = a0.x; As[nb][acol + 1][arow] = a0.y;
        As[nb][acol + 2][arow] = a0.z; As[nb][acol + 3][arow] = a0.w;
        As[nb][acol + 0][arow + 64] = a1.x; As[nb][acol + 1][arow + 64] = a1.y;
        As[nb][acol + 2][arow + 64] = a1.z; As[nb][acol + 3][arow + 64] = a1.w;
        *(float4*)&Bs[nb][brow][bcol]     = b0;
        *(float4*)&Bs[nb][brow + 8][bcol] = b1;
        __syncthreads();
        buf = nb;
    }
    gemm_compute(As[buf], Bs[buf], tm, tn, acc);

    // epilogue
#pragma unroll
    for (int i = 0; i < 8; ++i) {
        size_t r = (size_t)(bm + tm + i);
        float* cp = C + r * N + bn + tn;
        const float* rp = RES + r * N + bn + tn;
        float vals[8];
#pragma unroll
        for (int j = 0; j < 8; ++j) {
            float v = acc[i][j];
            if (EPI == 1) v += rp[j];
            if (EPI == 2) { v += BIAS[bn + tn + j]; v = v * normcdff(v); }
            if (EPI == 3) v += BIAS[bn + tn + j] + rp[j];
            vals[j] = v;
        }
        *(float4*)cp       = make_float4(vals[0], vals[1], vals[2], vals[3]);
        *(float4*)(cp + 4) = make_float4(vals[4], vals[5], vals[6], vals[7]);
    }
}

// ---------------------------------------------------------------------------
// K4: windowed attention. One block (256 thr) per window; loop over 8 heads.
// Reads OFF_QKV, writes OFF_ATTNO (heads merged token-major).
// ---------------------------------------------------------------------------
__global__ void __launch_bounds__(256) k_attn(const float* __restrict__ rpb)
{
    __shared__ float sq[64][32];
    __shared__ float sk[64][33];
    __shared__ float sv[64][33];
    __shared__ float sp[64][65];
    __shared__ float srpb[225 * 8];

    const int tid = threadIdx.x;
    const size_t tokbase = (size_t)blockIdx.x * 64;
    const float* qkv = g_scratch + OFF_QKV;
    float* outp = g_scratch + OFF_ATTNO;

    for (int i = tid; i < 1800; i += 256) srpb[i] = rpb[i];

    const int row = tid >> 2, c = tid & 3;
    const int ri = row >> 3, rj = row & 7;
    const float sc = 0.17677669529663687f; // 32^-0.5

    for (int h = 0; h < 8; ++h) {
        __syncthreads();  // protect smem reuse across heads (incl. srpb fill)
        // load q,k,v for this head
#pragma unroll
        for (int m = 0; m < 2; ++m) {
            int e = m * 256 + tid;
            int t = e >> 3, d4 = (e & 7) << 2;
            const float* src = qkv + (tokbase + t) * 768 + h * 32 + d4;
            float4 q4 = *(const float4*)src;
            float4 k4 = *(const float4*)(src + 256);
            float4 v4 = *(const float4*)(src + 512);
            q4.x *= sc; q4.y *= sc; q4.z *= sc; q4.w *= sc;
            *(float4*)&sq[t][d4] = q4;
            sk[t][d4 + 0] = k4.x; sk[t][d4 + 1] = k4.y;
            sk[t][d4 + 2] = k4.z; sk[t][d4 + 3] = k4.w;
            sv[t][d4 + 0] = v4.x; sv[t][d4 + 1] = v4.y;
            sv[t][d4 + 2] = v4.z; sv[t][d4 + 3] = v4.w;
        }
        __syncthreads();

        // sim row = q[row] . k[col], 16 cols per thread
        float s[16];
#pragma unroll
        for (int j = 0; j < 16; ++j) s[j] = 0.f;
#pragma unroll
        for (int d = 0; d < 32; ++d) {
            float qv = sq[row][d];
#pragma unroll
            for (int j = 0; j < 16; ++j)
                s[j] += qv * sk[c * 16 + j][d];
        }
        // + relative position bias
#pragma unroll
        for (int j = 0; j < 16; ++j) {
            int col = c * 16 + j;
            int idx = (ri - (col >> 3) + 7) * 15 + (rj - (col & 7) + 7);
            s[j] += srpb[idx * 8 + h];
        }
        // softmax across the 4-lane quad owning this row
        float mx = s[0];
#pragma unroll
        for (int j = 1; j < 16; ++j) mx = fmaxf(mx, s[j]);
        mx = fmaxf(mx, __shfl_xor_sync(0xffffffffu, mx, 1));
        mx = fmaxf(mx, __shfl_xor_sync(0xffffffffu, mx, 2));
        float sum = 0.f;
#pragma unroll
        for (int j = 0; j < 16; ++j) { s[j] = __expf(s[j] - mx); sum += s[j]; }
        sum += __shfl_xor_sync(0xffffffffu, sum, 1);
        sum += __shfl_xor_sync(0xffffffffu, sum, 2);
        float inv = 1.f / sum;
#pragma unroll
        for (int j = 0; j < 16; ++j) sp[row][c * 16 + j] = s[j] * inv;
        __syncthreads();

        // out[row][c*8 .. c*8+7] = sum_j p[row][j] * v[j][:]
        float o[8];
#pragma unroll
        for (int dd = 0; dd < 8; ++dd) o[dd] = 0.f;
#pragma unroll
        for (int jc = 0; jc < 64; ++jc) {
            float p = sp[row][jc];
#pragma unroll
            for (int dd = 0; dd < 8; ++dd)
                o[dd] += p * sv[jc][c * 8 + dd];
        }
        float* dst = outp + (tokbase + row) * 256 + h * 32 + c * 8;
        *(float4*)dst       = make_float4(o[0], o[1], o[2], o[3]);
        *(float4*)(dst + 4) = make_float4(o[4], o[5], o[6], o[7]);
    }
}

// ---------------------------------------------------------------------------
// Host launcher
// ---------------------------------------------------------------------------
extern "C" void kernel_launch(void* const* d_in, const int* in_sizes, int n_in,
                              void* d_out, int out_size)
{
    const float* x     = (const float*)d_in[0];
    const float* ln1_g = (const float*)d_in[1];
    const float* ln1_b = (const float*)d_in[2];
    const float* ln2_g = (const float*)d_in[3];
    const float* ln2_b = (const float*)d_in[4];
    const float* w_qkv = (const float*)d_in[5];
    const float* w_out = (const float*)d_in[6];
    const float* rpb   = (const float*)d_in[7];
    const float* ln3_g = (const float*)d_in[8];
    const float* ln3_b = (const float*)d_in[9];
    const float* w1    = (const float*)d_in[10];
    const float* b1    = (const float*)d_in[11];
    const float* w2    = (const float*)d_in[12];
    const float* b2    = (const float*)d_in[13];
    float* out = (float*)d_out;

    float* S = nullptr;
    cudaGetSymbolAddress((void**)&S, g_scratch);

    // 1. gather x -> xw (token-major)
    k_gather<<<4096, 256>>>(x);
    // 2. t = LN2(LN1(xw))
    k_ln12<<<4096, 256>>>(ln1_g, ln1_b, ln2_g, ln2_b);
    // 3. qkv = t @ w_qkv          [131072 x 768] = [131072 x 256] @ [256 x 768]
    k_gemm<0><<<dim3(6, 1024), 256>>>(S + OFF_T, w_qkv, S + OFF_QKV, S, S, 768, 256);
    // 4. windowed attention -> attno
    k_attn<<<2048, 256>>>(rpb);
    // 5. xw2 = attno @ w_out + xw
    k_gemm<1><<<dim3(2, 1024), 256>>>(S + OFF_ATTNO, w_out, S + OFF_XW2, S + OFF_XW, S, 256, 256);
    // 6. f = LN3(xw2)
    k_ln3<<<4096, 256>>>(ln3_g, ln3_b);
    // 7. h = gelu(f @ w1 + b1)    [131072 x 1024]
    k_gemm<2><<<dim3(8, 1024), 256>>>(S + OFF_F, w1, S + OFF_H, S, b1, 1024, 256);
    // 8. y = h @ w2 + b2 + xw2 -> OFF_T (reuse)
    k_gemm<3><<<dim3(2, 1024), 256>>>(S + OFF_H, w2, S + OFF_T, S + OFF_XW2, b2, 256, 1024);
    // 9. scatter y -> NCHW out
    k_scatter<<<4096, 256>>>(out);
}

// round 6
// speedup vs baseline: 1.9827x; 1.9808x over previous
#include <cuda_runtime.h>
#include <cstdint>
#include <cstddef>

#define NTOK 131072
constexpr size_t NT = (size_t)NTOK;
constexpr size_t OFF_XW    = 0;
constexpr size_t OFF_T     = NT * 256;
constexpr size_t OFF_QKV   = NT * 512;
constexpr size_t OFF_ATTNO = NT * 1280;
constexpr size_t OFF_XW2   = NT * 1536;
constexpr size_t OFF_F     = NT * 1792;
constexpr size_t OFF_H     = NT * 2048;
constexpr size_t OFF_BT_QKV = NT * 3072;           // 768x256
constexpr size_t OFF_BT_OUT = OFF_BT_QKV + 196608; // 256x256
constexpr size_t OFF_BT_W1  = OFF_BT_OUT + 65536;  // 1024x256
constexpr size_t OFF_BT_W2  = OFF_BT_W1 + 262144;  // 256x1024
__device__ float g_scratch[OFF_BT_W2 + 262144];

__device__ __forceinline__ uint32_t f2t(float x) {
    uint32_t u; asm("cvt.rna.tf32.f32 %0, %1;" : "=r"(u) : "f"(x)); return u;
}
__device__ __forceinline__ uint32_t smem_u32(const void* p) {
    uint32_t a;
    asm("{.reg .u64 t; cvta.to.shared.u64 t, %1; cvt.u32.u64 %0, t;}" : "=r"(a) : "l"(p));
    return a;
}
__device__ __forceinline__ void cpa16(uint32_t dst, const float* src) {
    asm volatile("cp.async.ca.shared.global [%0], [%1], 16;" :: "r"(dst), "l"(src));
}
__device__ __forceinline__ void mma8(float* d, const uint32_t* a, const uint32_t* b) {
    asm volatile(
        "mma.sync.aligned.m16n8k8.row.col.f32.tf32.tf32.f32 "
        "{%0,%1,%2,%3},{%4,%5,%6,%7},{%8,%9},{%0,%1,%2,%3};"
        : "+f"(d[0]), "+f"(d[1]), "+f"(d[2]), "+f"(d[3])
        : "r"(a[0]), "r"(a[1]), "r"(a[2]), "r"(a[3]), "r"(b[0]), "r"(b[1]));
}

// ---------------- weight transpose BT[n][k] = B[k][n] ----------------
__global__ void __launch_bounds__(256) k_transpose(
    const float* __restrict__ B, float* __restrict__ BT, int K, int N)
{
    __shared__ float t[32][33];
    int kb = blockIdx.y * 32, nb = blockIdx.x * 32;
    int tx = threadIdx.x & 31, ty = threadIdx.x >> 5;
    for (int i = ty; i < 32; i += 8) t[i][tx] = B[(size_t)(kb + i) * N + nb + tx];
    __syncthreads();
    for (int i = ty; i < 32; i += 8) BT[(size_t)(nb + i) * K + kb + tx] = t[tx][i];
}

// ---------------- gather / scatter NCHW <-> token-major ----------------
__global__ void __launch_bounds__(256) k_gather(const float* __restrict__ x)
{
    __shared__ float sm[256][33];
    int tid = threadIdx.x, bi = blockIdx.x;
    int dc = bi & 7, w1 = (bi >> 3) & 7, wx = (bi >> 6) & 31, b = bi >> 11;
    const float* xb = x + ((size_t)b * 256 + dc * 32) * 65536 + (size_t)(wx * 8 + w1) * 256;
#pragma unroll
    for (int it = 0; it < 32; ++it) sm[tid][it] = xb[(size_t)it * 65536 + tid];
    __syncthreads();
#pragma unroll
    for (int it = 0; it < 32; ++it) {
        int t = it * 8 + (tid >> 5), dd = tid & 31;
        size_t tok = (((size_t)b * 32 + wx) * 32 + (t >> 3)) * 64 + w1 * 8 + (t & 7);
        g_scratch[OFF_XW + tok * 256 + dc * 32 + dd] = sm[t][dd];
    }
}
__global__ void __launch_bounds__(256) k_scatter(float* __restrict__ out)
{
    __shared__ float sm[256][33];
    int tid = threadIdx.x, bi = blockIdx.x;
    int dc = bi & 7, w1 = (bi >> 3) & 7, wx = (bi >> 6) & 31, b = bi >> 11;
#pragma unroll
    for (int it = 0; it < 32; ++it) {
        int t = it * 8 + (tid >> 5), dd = tid & 31;
        size_t tok = (((size_t)b * 32 + wx) * 32 + (t >> 3)) * 64 + w1 * 8 + (t & 7);
        sm[t][dd] = g_scratch[OFF_T + tok * 256 + dc * 32 + dd];
    }
    __syncthreads();
    float* ob = out + ((size_t)b * 256 + dc * 32) * 65536 + (size_t)(wx * 8 + w1) * 256;
#pragma unroll
    for (int it = 0; it < 32; ++it) ob[(size_t)it * 65536 + tid] = sm[tid][it];
}

// ---------------- LayerNorm (TWO=1: LN2(LN1(x)); TWO=0: single LN) -------
template <int TWO>
__global__ void __launch_bounds__(256) k_ln(
    const float* __restrict__ src, float* __restrict__ dst,
    const float* __restrict__ g1, const float* __restrict__ b1,
    const float* __restrict__ g2, const float* __restrict__ b2)
{
    __shared__ float sm[8192], sg1[256], sb1[256], sg2[256], sb2[256], st1[32][2], st2[32][2];
    int tid = threadIdx.x;
    size_t base = (size_t)blockIdx.x * 8192;
    sg1[tid] = g1[tid]; sb1[tid] = b1[tid];
    if (TWO) { sg2[tid] = g2[tid]; sb2[tid] = b2[tid]; }
#pragma unroll
    for (int it = 0; it < 32; ++it) sm[it * 256 + tid] = src[base + it * 256 + tid];
    __syncthreads();
    int warp = tid >> 5, lane = tid & 31;
#pragma unroll
    for (int j = 0; j < 4; ++j) {
        int tok = warp * 4 + j;
        float s = 0.f, ss = 0.f;
#pragma unroll
        for (int m = 0; m < 8; ++m) {
            float v = sm[tok * 256 + lane + 32 * m]; s += v; ss += v * v;
        }
#pragma unroll
        for (int o = 16; o > 0; o >>= 1) {
            s += __shfl_xor_sync(~0u, s, o); ss += __shfl_xor_sync(~0u, ss, o);
        }
        float m1 = s * (1.f / 256.f), i1 = rsqrtf(ss * (1.f / 256.f) - m1 * m1 + 1e-5f);
        if (lane == 0) { st1[tok][0] = m1; st1[tok][1] = i1; }
        if (TWO) {
            float s2 = 0.f, ss2 = 0.f;
#pragma unroll
            for (int m = 0; m < 8; ++m) {
                int d = lane + 32 * m;
                float u = (sm[tok * 256 + d] - m1) * i1 * sg1[d] + sb1[d];
                s2 += u; ss2 += u * u;
            }
#pragma unroll
            for (int o = 16; o > 0; o >>= 1) {
                s2 += __shfl_xor_sync(~0u, s2, o); ss2 += __shfl_xor_sync(~0u, ss2, o);
            }
            if (lane == 0) {
                float m2 = s2 * (1.f / 256.f);
                st2[tok][0] = m2; st2[tok][1] = rsqrtf(ss2 * (1.f / 256.f) - m2 * m2 + 1e-5f);
            }
        }
    }
    __syncthreads();
#pragma unroll
    for (int tok = 0; tok < 32; ++tok) {
        float u = (sm[tok * 256 + tid] - st1[tok][0]) * st1[tok][1] * sg1[tid] + sb1[tid];
        if (TWO) u = (u - st2[tok][0]) * st2[tok][1] * sg2[tid] + sb2[tid];
        dst[base + tok * 256 + tid] = u;
    }
}

// ---------------- tf32 mma.sync GEMM: C[M,N]=A[M,K]@B, BT=[N,K] ----------
// tile 128x128, BK=32, 8 warps (warp tile 32x64), cp.async double-buffered.
// SMEM fp32 raw; cvt.rna.tf32 at fragment load. Stride 36 = conflict-free.
// EPI: 0 none | 1 +RES | 2 gelu(+BIAS) | 3 +BIAS+RES
#define GEMM_SMEM 73728
template <int EPI>
__global__ void __launch_bounds__(256) k_gemm_mma(
    const float* __restrict__ A, const float* __restrict__ BT,
    float* __restrict__ C, const float* __restrict__ RES,
    const float* __restrict__ BIAS, int N, int K)
{
    extern __shared__ float smf[];
    float* As = smf;            // [2][128][36]
    float* Bs = smf + 9216;
    const int tid = threadIdx.x, lane = tid & 31, wid = tid >> 5;
    const int bm = blockIdx.y << 7, bn = blockIdx.x << 7;
    const int wr = wid & 3, wc = wid >> 2;   // warp tile: rows wr*32, cols wc*64
    const int g = lane >> 2, q = lane & 3;

    const int lrow = tid >> 3, lkq = (tid & 7) << 2;
    const float* ApG = A  + (size_t)(bm + lrow) * K + lkq;
    const float* BpG = BT + (size_t)(bn + lrow) * K + lkq;
    const uint32_t sA = smem_u32(As), sB = smem_u32(Bs);
    const uint32_t soff = ((uint32_t)lrow * 36 + (uint32_t)lkq) * 4;

    float acc[2][8][4];
#pragma unroll
    for (int i = 0; i < 2; ++i)
#pragma unroll
        for (int j = 0; j < 8; ++j)
#pragma unroll
            for (int e = 0; e < 4; ++e) acc[i][j][e] = 0.f;

    // prefetch chunk 0
#pragma unroll
    for (int it = 0; it < 4; ++it) {
        cpa16(sA + soff + it * 32 * 36 * 4, ApG + (size_t)(it * 32) * K);
        cpa16(sB + soff + it * 32 * 36 * 4, BpG + (size_t)(it * 32) * K);
    }
    asm volatile("cp.async.commit_group;" ::: "memory");

    const int nc = K >> 5;
    for (int c = 0; c < nc; ++c) {
        if (c + 1 < nc) {
            const int kc = (c + 1) << 5;
            const uint32_t bo = (uint32_t)((c + 1) & 1) * 4608u * 4u;
#pragma unroll
            for (int it = 0; it < 4; ++it) {
                cpa16(sA + bo + soff + it * 32 * 36 * 4, ApG + (size_t)(it * 32) * K + kc);
                cpa16(sB + bo + soff + it * 32 * 36 * 4, BpG + (size_t)(it * 32) * K + kc);
            }
            asm volatile("cp.async.commit_group;" ::: "memory");
            asm volatile("cp.async.wait_group 1;" ::: "memory");
        } else {
            asm volatile("cp.async.wait_group 0;" ::: "memory");
        }
        __syncthreads();

        const float* Ab = As + (c & 1) * 4608 + (wr << 5) * 36;
        const float* Bb = Bs + (c & 1) * 4608 + (wc << 6) * 36;
#pragma unroll
        for (int ks = 0; ks < 4; ++ks) {
            const int kb = ks << 3;
            uint32_t bf[8][2];
#pragma unroll
            for (int nt = 0; nt < 8; ++nt) {
                bf[nt][0] = f2t(Bb[(nt * 8 + g) * 36 + kb + q]);
                bf[nt][1] = f2t(Bb[(nt * 8 + g) * 36 + kb + 4 + q]);
            }
#pragma unroll
            for (int mt = 0; mt < 2; ++mt) {
                uint32_t af[4];
                af[0] = f2t(Ab[(mt * 16 + g) * 36 + kb + q]);
                af[1] = f2t(Ab[(mt * 16 + 8 + g) * 36 + kb + q]);
                af[2] = f2t(Ab[(mt * 16 + g) * 36 + kb + 4 + q]);
                af[3] = f2t(Ab[(mt * 16 + 8 + g) * 36 + kb + 4 + q]);
#pragma unroll
                for (int nt = 0; nt < 8; ++nt) mma8(acc[mt][nt], af, bf[nt]);
            }
        }
        __syncthreads();   // all warps done reading buf before it is overwritten
    }

    // epilogue
#pragma unroll
    for (int mt = 0; mt < 2; ++mt) {
#pragma unroll
        for (int nt = 0; nt < 8; ++nt) {
            int row0 = bm + (wr << 5) + mt * 16 + g;
            int col  = bn + (wc << 6) + nt * 8 + q * 2;
            float v00 = acc[mt][nt][0], v01 = acc[mt][nt][1];
            float v10 = acc[mt][nt][2], v11 = acc[mt][nt][3];
            if (EPI == 2 || EPI == 3) {
                float2 bb = *(const float2*)(BIAS + col);
                v00 += bb.x; v01 += bb.y; v10 += bb.x; v11 += bb.y;
            }
            if (EPI == 1 || EPI == 3) {
                float2 r0 = *(const float2*)(RES + (size_t)row0 * N + col);
                float2 r1 = *(const float2*)(RES + (size_t)(row0 + 8) * N + col);
                v00 += r0.x; v01 += r0.y; v10 += r1.x; v11 += r1.y;
            }
            if (EPI == 2) {
                v00 *= normcdff(v00); v01 *= normcdff(v01);
                v10 *= normcdff(v10); v11 *= normcdff(v11);
            }
            *(float2*)(C + (size_t)row0 * N + col)       = make_float2(v00, v01);
            *(float2*)(C + (size_t)(row0 + 8) * N + col) = make_float2(v10, v11);
        }
    }
}

// ---------------- windowed attention (K transposed in SMEM) -------------
#define ATTN_SMEM (12552 * 4)
__global__ void __launch_bounds__(256) k_attn(const float* __restrict__ rpb)
{
    extern __shared__ float sa[];
    float (*sq)[33]  = (float(*)[33])sa;            // 64x33
    float (*skT)[68] = (float(*)[68])(sa + 2112);   // 32x68
    float (*sv)[36]  = (float(*)[36])(sa + 4288);   // 64x36
    float (*sp)[65]  = (float(*)[65])(sa + 6592);   // 64x65
    float* srpb      = sa + 10752;                  // 1800

    int tid = threadIdx.x;
    size_t tokbase = (size_t)blockIdx.x * 64;
    const float* qkv = g_scratch + OFF_QKV;
    float* outp = g_scratch + OFF_ATTNO;
    for (int i = tid; i < 1800; i += 256) srpb[i] = rpb[i];

    int row = tid >> 2, c = tid & 3;
    int ri = row >> 3, rj = row & 7;
    const float sc = 0.17677669529663687f;

    for (int h = 0; h < 8; ++h) {
        __syncthreads();
#pragma unroll
        for (int m = 0; m < 2; ++m) {
            int e = m * 256 + tid, t = e >> 3, d4 = (e & 7) << 2;
            const float* src = qkv + (tokbase + t) * 768 + h * 32 + d4;
            float4 q4 = *(const float4*)src;
            float4 k4 = *(const float4*)(src + 256);
            float4 v4 = *(const float4*)(src + 512);
            sq[t][d4] = q4.x * sc; sq[t][d4 + 1] = q4.y * sc;
            sq[t][d4 + 2] = q4.z * sc; sq[t][d4 + 3] = q4.w * sc;
            skT[d4][t] = k4.x; skT[d4 + 1][t] = k4.y;
            skT[d4 + 2][t] = k4.z; skT[d4 + 3][t] = k4.w;
            *(float4*)&sv[t][d4] = v4;
        }
        __syncthreads();

        float s[16];
#pragma unroll
        for (int j = 0; j < 16; ++j) s[j] = 0.f;
#pragma unroll
        for (int d = 0; d < 32; ++d) {
            float qv = sq[row][d];
#pragma unroll
            for (int m = 0; m < 4; ++m) {
                float4 kk = *(const float4*)&skT[d][c * 16 + m * 4];
                s[m * 4] += qv * kk.x; s[m * 4 + 1] += qv * kk.y;
                s[m * 4 + 2] += qv * kk.z; s[m * 4 + 3] += qv * kk.w;
            }
        }
#pragma unroll
        for (int j = 0; j < 16; ++j) {
            int col = c * 16 + j;
            s[j] += srpb[((ri - (col >> 3) + 7) * 15 + (rj - (col & 7) + 7)) * 8 + h];
        }
        float mx = s[0];
#pragma unroll
        for (int j = 1; j < 16; ++j) mx = fmaxf(mx, s[j]);
        mx = fmaxf(mx, __shfl_xor_sync(~0u, mx, 1));
        mx = fmaxf(mx, __shfl_xor_sync(~0u, mx, 2));
        float sum = 0.f;
#pragma unroll
        for (int j = 0; j < 16; ++j) { s[j] = __expf(s[j] - mx); sum += s[j]; }
        sum += __shfl_xor_sync(~0u, sum, 1);
        sum += __shfl_xor_sync(~0u, sum, 2);
        float inv = 1.f / sum;
#pragma unroll
        for (int j = 0; j < 16; ++j) sp[row][c * 16 + j] = s[j] * inv;
        __syncthreads();

        float o[8];
#pragma unroll
        for (int dd = 0; dd < 8; ++dd) o[dd] = 0.f;
#pragma unroll
        for (int jc = 0; jc < 64; ++jc) {
            float p = sp[row][jc];
            float4 v0 = *(const float4*)&sv[jc][c * 8];
            float4 v1 = *(const float4*)&sv[jc][c * 8 + 4];
            o[0] += p * v0.x; o[1] += p * v0.y; o[2] += p * v0.z; o[3] += p * v0.w;
            o[4] += p * v1.x; o[5] += p * v1.y; o[6] += p * v1.z; o[7] += p * v1.w;
        }
        float* dst = outp + (tokbase + row) * 256 + h * 32 + c * 8;
        *(float4*)dst       = make_float4(o[0], o[1], o[2], o[3]);
        *(float4*)(dst + 4) = make_float4(o[4], o[5], o[6], o[7]);
    }
}

// ---------------- host launcher ----------------
extern "C" void kernel_launch(void* const* d_in, const int* in_sizes, int n_in,
                              void* d_out, int out_size)
{
    const float* x     = (const float*)d_in[0];
    const float* ln1_g = (const float*)d_in[1];
    const float* ln1_b = (const float*)d_in[2];
    const float* ln2_g = (const float*)d_in[3];
    const float* ln2_b = (const float*)d_in[4];
    const float* w_qkv = (const float*)d_in[5];
    const float* w_out = (const float*)d_in[6];
    const float* rpb   = (const float*)d_in[7];
    const float* ln3_g = (const float*)d_in[8];
    const float* ln3_b = (const float*)d_in[9];
    const float* w1    = (const float*)d_in[10];
    const float* b1    = (const float*)d_in[11];
    const float* w2    = (const float*)d_in[12];
    const float* b2    = (const float*)d_in[13];
    float* out = (float*)d_out;

    float* S = nullptr;
    cudaGetSymbolAddress((void**)&S, g_scratch);

    cudaFuncSetAttribute(k_gemm_mma<0>, cudaFuncAttributeMaxDynamicSharedMemorySize, GEMM_SMEM);
    cudaFuncSetAttribute(k_gemm_mma<1>, cudaFuncAttributeMaxDynamicSharedMemorySize, GEMM_SMEM);
    cudaFuncSetAttribute(k_gemm_mma<2>, cudaFuncAttributeMaxDynamicSharedMemorySize, GEMM_SMEM);
    cudaFuncSetAttribute(k_gemm_mma<3>, cudaFuncAttributeMaxDynamicSharedMemorySize, GEMM_SMEM);
    cudaFuncSetAttribute(k_attn, cudaFuncAttributeMaxDynamicSharedMemorySize, ATTN_SMEM);

    k_transpose<<<dim3(24, 8), 256>>>(w_qkv, S + OFF_BT_QKV, 256, 768);
    k_transpose<<<dim3(8, 8), 256>>>(w_out, S + OFF_BT_OUT, 256, 256);
    k_transpose<<<dim3(32, 8), 256>>>(w1, S + OFF_BT_W1, 256, 1024);
    k_transpose<<<dim3(8, 32), 256>>>(w2, S + OFF_BT_W2, 1024, 256);

    k_gather<<<4096, 256>>>(x);
    k_ln<1><<<4096, 256>>>(S + OFF_XW, S + OFF_T, ln1_g, ln1_b, ln2_g, ln2_b);
    k_gemm_mma<0><<<dim3(6, 1024), 256, GEMM_SMEM>>>(
        S + OFF_T, S + OFF_BT_QKV, S + OFF_QKV, S, S, 768, 256);
    k_attn<<<2048, 256, ATTN_SMEM>>>(rpb);
    k_gemm_mma<1><<<dim3(2, 1024), 256, GEMM_SMEM>>>(
        S + OFF_ATTNO, S + OFF_BT_OUT, S + OFF_XW2, S + OFF_XW, S, 256, 256);
    k_ln<0><<<4096, 256>>>(S + OFF_XW2, S + OFF_F, ln3_g, ln3_b, ln3_g, ln3_b);
    k_gemm_mma<2><<<dim3(8, 1024), 256, GEMM_SMEM>>>(
        S + OFF_F, S + OFF_BT_W1, S + OFF_H, S, b1, 1024, 256);
    k_gemm_mma<3><<<dim3(2, 1024), 256, GEMM_SMEM>>>(
        S + OFF_H, S + OFF_BT_W2, S + OFF_T, S + OFF_XW2, b2, 256, 1024);
    k_scatter<<<4096, 256>>>(out);
}